// round 5
// baseline (speedup 1.0000x reference)
#include <cuda_runtime.h>
#include <math_constants.h>

// SPP: out = concat(x, pool5(x), pool9(x), pool13(x)) along channels.
// Cascade: pool9 = pool5(pool5(x)), pool13 = pool5(pool9(x)), each separable.
//
// One WARP handles TWO (n,c) 32x32 planes (16 lanes each, width-16 shuffles).
// Each lane owns 2 columns x 32 rows as float2 registers. Horizontal 5-max
// via pair-max factorization (4 SHFL per warp-row for 2 plane-rows);
// vertical 5-max via register ring. Zero smem, zero barriers.
//
// R4 change: streaming cache hints. All output stores use __stcs (evict-
// first) so L2 write-back drains in store order (long DRAM bursts) and the
// 268 MB write stream doesn't evict the L2-resident input. Input loads use
// __ldcs. This kernel is a pure write-drain workload: 268 MB out vs 67 MB
// (L2-resident) in.
//
// x: (32, 512, 32, 32) f32 -> out: (32, 2048, 32, 32) f32.

#define NCHAN 512
#define HW 1024
#define PLANES (32 * 512)
#define WARPS_PER_BLK 8
#define PLANES_PER_BLK (WARPS_PER_BLK * 2)

__global__ __launch_bounds__(32 * WARPS_PER_BLK)
void spp_kernel(const float* __restrict__ x, float* __restrict__ out) {
    const int lane = threadIdx.x & 31;
    const int wid  = threadIdx.x >> 5;
    const int sub  = lane >> 4;          // which plane within the warp (0/1)
    const int l    = lane & 15;          // column-pair index: cols 2l, 2l+1

    const int plane = blockIdx.x * PLANES_PER_BLK + wid * 2 + sub; // n*512+c
    const int n = plane >> 9;
    const int c = plane & (NCHAN - 1);

    const float2* __restrict__ xin =
        (const float2*)(x + (size_t)plane * HW) + l;
    float2* __restrict__ ob =
        (float2*)(out + ((size_t)n * (4 * NCHAN) + c) * HW) + l;

    // Lane's 2-column strip, all 32 rows, in registers.
    // Pass-through (section 0) fused into the load loop.
    float2 v[32];
    #pragma unroll
    for (int y = 0; y < 32; ++y) {
        v[y] = __ldcs(&xin[y * 16]);
        __stcs(&ob[y * 16], v[y]);
    }

    const unsigned FULL = 0xffffffffu;
    const float NEG = -CUDART_INF_F;

    #pragma unroll
    for (int p = 0; p < 3; ++p) {
        float2* __restrict__ obp = ob + (size_t)(p + 1) * NCHAN * (HW / 2);

        // vertical ring over h-rows: r0=h[y-4] .. r3=h[y-1]
        float2 r0 = {NEG, NEG}, r1 = {NEG, NEG},
               r2 = {NEG, NEG}, r3 = {NEG, NEG};

        #pragma unroll
        for (int y = 0; y < 34; ++y) {
            float2 h;
            if (y < 32) {
                const float a = v[y].x, b = v[y].y;
                const float pm = fmaxf(a, b);
                // width=16: shuffles stay inside this plane's lane segment;
                // OOB-in-segment returns own value (duplicate under max).
                const float lp = __shfl_up_sync  (FULL, pm, 1, 16); // max(la,lb)
                const float lb = __shfl_up_sync  (FULL, b,  1, 16); // col 2l-1
                const float ra = __shfl_down_sync(FULL, a,  1, 16); // col 2l+2
                const float rp = __shfl_down_sync(FULL, pm, 1, 16); // max(ra,rb)
                h.x = fmaxf(fmaxf(lp, pm), ra);   // cols 2l-2 .. 2l+2
                h.y = fmaxf(fmaxf(lb, pm), rp);   // cols 2l-1 .. 2l+3
            } else {
                h.x = NEG; h.y = NEG;             // bottom padding rows
            }

            if (y >= 2) {
                float2 m;
                m.x = fmaxf(fmaxf(fmaxf(r0.x, r1.x), fmaxf(r2.x, r3.x)), h.x);
                m.y = fmaxf(fmaxf(fmaxf(r0.y, r1.y), fmaxf(r2.y, r3.y)), h.y);
                v[y - 2] = m;                     // in-place: feeds next pool
                __stcs(&obp[(y - 2) * 16], m);
            }

            r0 = r1; r1 = r2; r2 = r3; r3 = h;    // renamed by full unroll
        }
    }
}

extern "C" void kernel_launch(void* const* d_in, const int* in_sizes, int n_in,
                              void* d_out, int out_size) {
    const float* x = (const float*)d_in[0];
    float* out     = (float*)d_out;
    spp_kernel<<<PLANES / PLANES_PER_BLK, 32 * WARPS_PER_BLK>>>(x, out);
}

// round 6
// speedup vs baseline: 1.7603x; 1.7603x over previous
#include <cuda_runtime.h>
#include <math_constants.h>

// SPP: out = concat(x, pool5(x), pool9(x), pool13(x)) along channels.
// Cascade: pool9 = pool5(pool5(x)), pool13 = pool5(pool9(x)), separable.
//
// R5 layout: one WARP handles FOUR (n,c) 32x32 planes. 8 lanes per plane
// (width-8 shuffles); each lane owns 4 columns x 32 rows as float4 regs.
// All global I/O is 128-bit (LDG.128 / STG.128) to minimize LSU issue cost,
// which co-binds with DRAM write drain. Horizontal 5-max: 4 width-8 shuffles
// + explicit -INF clipping at plane edges (shuffle self-return is no longer
// inside the window at 4 cols/lane). Vertical 5-max: register ring.
// No smem, no barriers, no cache hints (R4: __stcs on sub-line stores
// catastrophically defeats L2 write coalescing — never again).
//
// x: (32, 512, 32, 32) f32 -> out: (32, 2048, 32, 32) f32.

#define NCHAN 512
#define HW 1024
#define PLANES (32 * 512)
#define WARPS_PER_BLK 4
#define PLANES_PER_BLK (WARPS_PER_BLK * 4)

__device__ __forceinline__ float4 fmax4(float4 a, float4 b) {
    return make_float4(fmaxf(a.x, b.x), fmaxf(a.y, b.y),
                       fmaxf(a.z, b.z), fmaxf(a.w, b.w));
}

__global__ __launch_bounds__(32 * WARPS_PER_BLK)
void spp_kernel(const float* __restrict__ x, float* __restrict__ out) {
    const int lane = threadIdx.x & 31;
    const int wid  = threadIdx.x >> 5;
    const int sub  = lane >> 3;          // plane within warp (0..3)
    const int l    = lane & 7;           // column-quad index: cols 4l..4l+3

    const bool ledge = (l == 0);
    const bool redge = (l == 7);

    const int plane = blockIdx.x * PLANES_PER_BLK + wid * 4 + sub; // n*512+c
    const int n = plane >> 9;
    const int c = plane & (NCHAN - 1);

    const float4* __restrict__ xin =
        (const float4*)(x + (size_t)plane * HW) + l;
    float4* __restrict__ ob =
        (float4*)(out + ((size_t)n * (4 * NCHAN) + c) * HW) + l;

    // Lane's 4-column strip, all 32 rows, in registers.
    // Pass-through (concat section 0) fused into the load loop.
    float4 v[32];
    #pragma unroll
    for (int y = 0; y < 32; ++y) {
        v[y] = xin[y * 8];
        ob[y * 8] = v[y];
    }

    const unsigned FULL = 0xffffffffu;
    const float NEG = -CUDART_INF_F;
    const float4 NEG4 = {NEG, NEG, NEG, NEG};

    #pragma unroll
    for (int p = 0; p < 3; ++p) {
        float4* __restrict__ obp = ob + (size_t)(p + 1) * NCHAN * (HW / 4);

        // vertical ring over h-rows: r0=h[y-4] .. r3=h[y-1]
        float4 r0 = NEG4, r1 = NEG4, r2 = NEG4, r3 = NEG4;

        #pragma unroll
        for (int y = 0; y < 34; ++y) {
            float4 h;
            if (y < 32) {
                const float a0 = v[y].x, a1 = v[y].y,
                            a2 = v[y].z, a3 = v[y].w;
                const float p01 = fmaxf(a0, a1);
                const float p23 = fmaxf(a2, a3);
                // width-8: shuffles stay inside this plane's lane segment.
                float Lp = __shfl_up_sync  (FULL, p23, 1, 8); // max(cols-2,-1)
                float L3 = __shfl_up_sync  (FULL, a3,  1, 8); // col 4l-1
                float R0 = __shfl_down_sync(FULL, a0,  1, 8); // col 4l+4
                float Rp = __shfl_down_sync(FULL, p01, 1, 8); // max(+4,+5)
                // Clip at plane edges (self-returned values are outside the
                // 5-window here, unlike the 1-2 col/lane variants).
                if (ledge) { Lp = NEG; L3 = NEG; }
                if (redge) { R0 = NEG; Rp = NEG; }

                const float m = fmaxf(p01, p23);       // max(a0..a3)
                h.x = fmaxf(Lp, fmaxf(p01, a2));        // cols 4l-2..4l+2
                h.y = fmaxf(L3, m);                     // cols 4l-1..4l+3
                h.z = fmaxf(m, R0);                     // cols 4l  ..4l+4
                h.w = fmaxf(fmaxf(a1, p23), Rp);        // cols 4l+1..4l+5
            } else {
                h = NEG4;                               // bottom padding
            }

            if (y >= 2) {
                float4 m4 = fmax4(fmax4(fmax4(r0, r1), fmax4(r2, r3)), h);
                v[y - 2] = m4;                          // feeds next pool
                obp[(y - 2) * 8] = m4;
            }

            r0 = r1; r1 = r2; r2 = r3; r3 = h;          // renamed by unroll
        }
    }
}

extern "C" void kernel_launch(void* const* d_in, const int* in_sizes, int n_in,
                              void* d_out, int out_size) {
    const float* x = (const float*)d_in[0];
    float* out     = (float*)d_out;
    spp_kernel<<<PLANES / PLANES_PER_BLK, 32 * WARPS_PER_BLK>>>(x, out);
}

// round 7
// speedup vs baseline: 1.9814x; 1.1256x over previous
#include <cuda_runtime.h>
#include <math_constants.h>
#include <cstdint>

// SPP: out = concat(x, pool5(x), pool9(x), pool13(x)) along channels.
// Cascade: pool9 = pool5(pool5(x)), pool13 = pool5(pool9(x)), separable.
//
// Compute core = R3 (best so far): one warp = two (n,c) planes, 16 lanes
// each (width-16 shuffles, OOB self-return free edge handling), lane owns
// 2 cols x 32 rows as float2 regs; horizontal 5-max via pair-max
// factorization (4 SHFL / warp-row / 2 plane-rows); vertical 5-max via
// register ring; in-place cascade.
//
// R6 change: OUTPUT PATH. Instead of per-warp STG (plateaus ~5.2 TB/s with
// DRAM idle 34%), each block stages one output section (8 contiguous
// planes = 32 KB) in SMEM and emits ONE cp.async.bulk.global.shared::cta
// (bulk/TMA store engine: full-line sequential writes, deep queueing).
// Double-buffered so pool-(p+1) compute overlaps section-p drain.
//
// x: (32, 512, 32, 32) f32 -> out: (32, 2048, 32, 32) f32.

#define NCHAN 512
#define HW 1024
#define PLANES (32 * 512)
#define WARPS_PER_BLK 4
#define PLANES_PER_BLK (WARPS_PER_BLK * 2)
#define SEC_FLOATS (PLANES_PER_BLK * HW)          // 8192 floats
#define SEC_BYTES  (SEC_FLOATS * 4)               // 32768 bytes
#define SMEM_BYTES (2 * SEC_BYTES)                // 64 KB

__device__ __forceinline__ uint32_t smem_u32(const void* p) {
    uint32_t a;
    asm("{ .reg .u64 t; cvta.to.shared.u64 t, %1; cvt.u32.u64 %0, t; }"
        : "=r"(a) : "l"(p));
    return a;
}

__global__ __launch_bounds__(32 * WARPS_PER_BLK)
void spp_kernel(const float* __restrict__ x, float* __restrict__ out) {
    extern __shared__ float sbuf[];               // [2][SEC_FLOATS]

    const int lane = threadIdx.x & 31;
    const int wid  = threadIdx.x >> 5;
    const int sub  = lane >> 4;                   // plane within warp (0/1)
    const int l    = lane & 15;                   // column-pair index

    const int pl_local = wid * 2 + sub;           // 0..7 within block
    const int plane = blockIdx.x * PLANES_PER_BLK + pl_local;   // n*512+c
    const int n  = plane >> 9;
    const int c0 = (blockIdx.x * PLANES_PER_BLK) & (NCHAN - 1); // block ch0

    const float2* __restrict__ xin =
        (const float2*)(x + (size_t)plane * HW) + l;

    // Lane's 2-column strip, all 32 rows, in registers.
    float2 v[32];
    #pragma unroll
    for (int y = 0; y < 32; ++y) v[y] = xin[y * 16];

    // Staging pointers (this lane's slot in each buffer).
    float2* stg0 = (float2*)(sbuf)              + pl_local * (HW / 2) + l;
    float2* stg1 = (float2*)(sbuf + SEC_FLOATS) + pl_local * (HW / 2) + l;

    // ---- section 0: pass-through copy via bulk store ----
    #pragma unroll
    for (int y = 0; y < 32; ++y) stg0[y * 16] = v[y];
    asm volatile("fence.proxy.async.shared::cta;" ::: "memory");
    __syncthreads();
    if (threadIdx.x == 0) {
        const float* dst = out + ((size_t)n * (4 * NCHAN) + c0) * HW;
        uint32_t s = smem_u32(sbuf);
        int bytes = SEC_BYTES;
        asm volatile("cp.async.bulk.global.shared::cta.bulk_group [%0], [%1], %2;"
                     :: "l"(dst), "r"(s), "r"(bytes) : "memory");
        asm volatile("cp.async.bulk.commit_group;" ::: "memory");
    }

    const unsigned FULL = 0xffffffffu;
    const float NEG = -CUDART_INF_F;

    #pragma unroll
    for (int p = 0; p < 3; ++p) {
        // ---- compute pool p in registers (overlaps prior bulk drain) ----
        float2 r0 = {NEG, NEG}, r1 = {NEG, NEG},
               r2 = {NEG, NEG}, r3 = {NEG, NEG};

        #pragma unroll
        for (int y = 0; y < 34; ++y) {
            float2 h;
            if (y < 32) {
                const float a = v[y].x, b = v[y].y;
                const float pm = fmaxf(a, b);
                const float lp = __shfl_up_sync  (FULL, pm, 1, 16);
                const float lb = __shfl_up_sync  (FULL, b,  1, 16);
                const float ra = __shfl_down_sync(FULL, a,  1, 16);
                const float rp = __shfl_down_sync(FULL, pm, 1, 16);
                h.x = fmaxf(fmaxf(lp, pm), ra);   // cols 2l-2 .. 2l+2
                h.y = fmaxf(fmaxf(lb, pm), rp);   // cols 2l-1 .. 2l+3
            } else {
                h.x = NEG; h.y = NEG;
            }
            if (y >= 2) {
                float2 m;
                m.x = fmaxf(fmaxf(fmaxf(r0.x, r1.x), fmaxf(r2.x, r3.x)), h.x);
                m.y = fmaxf(fmaxf(fmaxf(r0.y, r1.y), fmaxf(r2.y, r3.y)), h.y);
                v[y - 2] = m;                     // in-place: feeds next pool
            }
            r0 = r1; r1 = r2; r2 = r3; r3 = h;
        }

        // ---- stage + bulk store section p+1 (buffers alternate 1,0,1) ----
        const int b = (p + 1) & 1;
        if (p >= 1) {
            // Buffer b was used two sections ago; ensure its bulk read done.
            if (threadIdx.x == 0)
                asm volatile("cp.async.bulk.wait_group.read 1;" ::: "memory");
        }
        __syncthreads();                          // buffer-free known to all

        float2* stg = b ? stg1 : stg0;
        #pragma unroll
        for (int y = 0; y < 32; ++y) stg[y * 16] = v[y];
        asm volatile("fence.proxy.async.shared::cta;" ::: "memory");
        __syncthreads();

        if (threadIdx.x == 0) {
            const float* dst =
                out + ((size_t)n * (4 * NCHAN) + (size_t)(p + 1) * NCHAN + c0) * HW;
            uint32_t s = smem_u32(sbuf + (size_t)b * SEC_FLOATS);
            int bytes = SEC_BYTES;
            asm volatile("cp.async.bulk.global.shared::cta.bulk_group [%0], [%1], %2;"
                         :: "l"(dst), "r"(s), "r"(bytes) : "memory");
            asm volatile("cp.async.bulk.commit_group;" ::: "memory");
        }
    }

    // SMEM must outlive all pending bulk reads.
    if (threadIdx.x == 0)
        asm volatile("cp.async.bulk.wait_group.read 0;" ::: "memory");
    __syncthreads();
}

extern "C" void kernel_launch(void* const* d_in, const int* in_sizes, int n_in,
                              void* d_out, int out_size) {
    const float* x = (const float*)d_in[0];
    float* out     = (float*)d_out;
    cudaFuncSetAttribute(spp_kernel,
                         cudaFuncAttributeMaxDynamicSharedMemorySize, SMEM_BYTES);
    spp_kernel<<<PLANES / PLANES_PER_BLK, 32 * WARPS_PER_BLK, SMEM_BYTES>>>(x, out);
}